// round 14
// baseline (speedup 1.0000x reference)
#include <cuda_runtime.h>
#include <cuda_bf16.h>
#include <cstdint>
#include <stdint.h>
#include <math.h>

#define N 8192
#define D 64
#define LAM 0.5f
#define EPS 1e-8f
#define NT 64
#define NPAIRS 2080
#define NSM 148

// ---------------- device scratch ----------------
__device__ uint16_t g_zn_mp[N * 32];   // e4m3-packed normalized rows (64 B/row)
__device__ uint16_t g_zn_sc[N * 32];
__device__ float g_prow_sum[NT][N];
__device__ float g_prow_pos[NT][N];
__device__ float g_pcol_sum[NT][N];
__device__ float g_pcol_pos[NT][N];
__device__ float g_blocksum[256];

// smem layout (dynamic)
#define OFF_RING 0                    // 16 slots x 8192 = 131072
#define OFF_AF   131072               // A frags, 2 phases x 8192
#define OFF_BF   147456               // B frags, 2 phases x 8192
#define OFF_PB   163840               // P bits 2048
#define OFF_QB   165888               // Q bits 2048
#define OFF_RRS  167936               // RedRowS [128][4]
#define OFF_RRP  169984
#define OFF_RCS  172032
#define OFF_RCP  174080
#define SMEM_BYTES 176128

__device__ __forceinline__ float exp_tau(float x) {
    float y = x * 1.80336880f;   // (1/0.8) * log2(e)
    float r;
    asm("ex2.approx.ftz.f32 %0, %1;" : "=f"(r) : "f"(y));
    return r;
}

__device__ __forceinline__ void mma_fp8(float* c, const uint4& a, const uint2& b) {
    asm volatile(
        "mma.sync.aligned.m16n8k32.row.col.f32.e4m3.e4m3.f32 "
        "{%0,%1,%2,%3}, {%4,%5,%6,%7}, {%8,%9}, {%0,%1,%2,%3};"
        : "+f"(c[0]), "+f"(c[1]), "+f"(c[2]), "+f"(c[3])
        : "r"(a.x), "r"(a.y), "r"(a.z), "r"(a.w), "r"(b.x), "r"(b.y));
}

__device__ __forceinline__ uint32_t smem_u32(const void* p) {
    uint32_t a;
    asm("{ .reg .u64 t; cvta.to.shared.u64 t, %1; cvt.u32.u64 %0, t; }"
        : "=r"(a) : "l"(p));
    return a;
}

// pid -> (b0, b1), b0 <= b1, via closed-form + correction
__device__ __forceinline__ void decode_pair(int pid, int& b0, int& b1) {
    if (pid > NPAIRS - 1) pid = NPAIRS - 1;
    float disc = 4160.25f - 2.0f * (float)pid;   // 64.5^2 - 2 pid
    int b = (int)(64.5f - sqrtf(disc));
    if (b < 0) b = 0;
    if (b > 63) b = 63;
    int off = b * NT - (b * (b - 1)) / 2;
    if (off > pid) {
        b--;
        off = b * NT - (b * (b - 1)) / 2;
    } else if (b < 63) {
        int off2 = (b + 1) * NT - ((b + 1) * b) / 2;
        if (off2 <= pid) { b++; off = off2; }
    }
    b0 = b;
    b1 = b + (pid - off);
}

// ---------------- kernel 1: normalize + quantize to e4m3 ----------------
__global__ void normalize_kernel(const float* __restrict__ zmp,
                                 const float* __restrict__ zsc) {
    int gwarp = (blockIdx.x * blockDim.x + threadIdx.x) >> 5;
    int lane = threadIdx.x & 31;
    const float* src;
    uint16_t* dst;
    if (gwarp < N) {
        src = zmp + (size_t)gwarp * D;
        dst = g_zn_mp + (size_t)gwarp * 32;
    } else {
        src = zsc + (size_t)(gwarp - N) * D;
        dst = g_zn_sc + (size_t)(gwarp - N) * 32;
    }
    float2 v = *(const float2*)(src + 2 * lane);
    float s = v.x * v.x + v.y * v.y;
#pragma unroll
    for (int off = 16; off > 0; off >>= 1)
        s += __shfl_xor_sync(0xFFFFFFFF, s, off);
    float inv = rsqrtf(s);
    uint16_t packed;
    asm("cvt.rn.satfinite.e4m3x2.f32 %0, %1, %2;"
        : "=h"(packed) : "f"(v.y * inv), "f"(v.x * inv));
    dst[lane] = packed;
}

// issue one 8KB pos chunk (16 rows x 512B) via cp.async; one 16B seg per thread
__device__ __forceinline__ void issue_chunk(uint32_t sb, const int* __restrict__ pos,
                                            int lg, int total, int b0n, int b1n) {
    uint32_t dst = sb + OFF_RING + (uint32_t)(lg & 15) * 8192u + threadIdx.x * 16u;
    const int* src;
    if (lg < total) {
        int c = lg & 15;
        int o = c >> 3;                       // 0 = P, 1 = Q
        int row = (c & 7) * 16 + (threadIdx.x >> 5);
        int rb = o ? b1n : b0n;
        int cbx = o ? b0n : b1n;
        src = pos + (size_t)(rb * 128 + row) * N + cbx * 128 + (threadIdx.x & 31) * 4;
    } else {
        src = pos + threadIdx.x * 4;          // dummy (keeps pending invariant)
    }
    asm volatile("cp.async.cg.shared.global [%0], [%1], 16;" :: "r"(dst), "l"(src));
    asm volatile("cp.async.commit_group;" ::: "memory");
}

// ---------------- kernel 2: persistent symmetric-pair kernel ----------------
__global__ __launch_bounds__(512, 1)
void pair_kernel(const int* __restrict__ pos) {
    extern __shared__ char smem[];
    const uint32_t sb = smem_u32(smem);
    unsigned* Pbits = (unsigned*)(smem + OFF_PB);
    unsigned* Qbits = (unsigned*)(smem + OFF_QB);
    float* RedRowS = (float*)(smem + OFF_RRS);
    float* RedRowP = (float*)(smem + OFF_RRP);
    float* RedColS = (float*)(smem + OFF_RCS);
    float* RedColP = (float*)(smem + OFF_RCP);

    const int tid = threadIdx.x;
    const int lane = tid & 31;
    const int wid = tid >> 5;          // 0..15
    const int wm = wid >> 2;           // 0..3 : 32-row slab
    const int wn = wid & 3;            // 0..3 : 32-col slab
    const int q = lane >> 2, l4 = lane & 3;
    const int bid = blockIdx.x;

    const int nlocal = (NPAIRS - 1 - bid) / NSM + 1;   // 14 or 15 pairs
    const int total = nlocal * 16;

    int b0c, b1c, b0n, b1n;
    decode_pair(bid, b0c, b1c);
    decode_pair(bid + NSM, b0n, b1n);

    // prologue: fill the 16-deep ring with pair 0's chunks (pending = 16)
    for (int lg = 0; lg < 16; lg++) issue_chunk(sb, pos, lg, total, b0c, b1c);

    const int sh = (lane & 7) * 4;

    for (int i = 0; i < nlocal; i++) {
        // ---- z prefetch into registers (L2-hot), consumed after pack loop ----
        const int m = tid >> 2, c4 = tid & 3;
        const char* A0g = (const char*)g_zn_mp + (size_t)(b0c * 128) * 64;
        const char* B0g = (const char*)g_zn_sc + (size_t)(b1c * 128) * 64;
        const char* A1g = (const char*)g_zn_mp + (size_t)(b1c * 128) * 64;
        const char* B1g = (const char*)g_zn_sc + (size_t)(b0c * 128) * 64;
        uint4 za0 = *(const uint4*)(A0g + m * 64 + c4 * 16);
        uint4 zb0 = *(const uint4*)(B0g + m * 64 + c4 * 16);
        uint4 za1 = *(const uint4*)(A1g + m * 64 + c4 * 16);
        uint4 zb1 = *(const uint4*)(B1g + m * 64 + c4 * 16);

        // ---- pack this pair's 16 chunks; keep prefetching next pair ----
        for (int c = 0; c < 16; c++) {
            int lg = i * 16 + c;
            asm volatile("cp.async.wait_group 15;" ::: "memory");  // chunk lg arrived
            uint4 v = *(const uint4*)(smem + OFF_RING + (lg & 15) * 8192 + tid * 16);
            unsigned w = (unsigned)((v.x & 1) | ((v.y & 1) << 1) | ((v.z & 1) << 2) |
                                    ((v.w & 1) << 3)) << sh;
            w |= __shfl_xor_sync(0xFFFFFFFF, w, 1);
            w |= __shfl_xor_sync(0xFFFFFFFF, w, 2);
            w |= __shfl_xor_sync(0xFFFFFFFF, w, 4);
            if ((lane & 7) == 0) {
                int o = c >> 3;
                int row = (c & 7) * 16 + wid;
                unsigned* bits = o ? Qbits : Pbits;
                bits[row * 4 + (lane >> 3)] = w;
            }
            issue_chunk(sb, pos, lg + 16, total, b0n, b1n);   // always next pair
        }

        // ---- store z frags (fp8 m16n8k32 fragment layout) ----
        {
            int ks = c4 >> 1, kh = c4 & 1;
            int aoff = ((ks * 8 + (m >> 4)) * 32 + (m & 7) * 4) * 4 + ((m >> 3) & 1) + 2 * kh;
            int boff = ((ks * 16 + (m >> 3)) * 32 + (m & 7) * 4) * 2 + kh;
            uint32_t* Af0 = (uint32_t*)(smem + OFF_AF);
            uint32_t* Af1 = (uint32_t*)(smem + OFF_AF + 8192);
            uint32_t* Bf0 = (uint32_t*)(smem + OFF_BF);
            uint32_t* Bf1 = (uint32_t*)(smem + OFF_BF + 8192);
            Af0[aoff] = za0.x; Af0[aoff + 4] = za0.y; Af0[aoff + 8] = za0.z; Af0[aoff + 12] = za0.w;
            Af1[aoff] = za1.x; Af1[aoff + 4] = za1.y; Af1[aoff + 8] = za1.z; Af1[aoff + 12] = za1.w;
            Bf0[boff] = zb0.x; Bf0[boff + 2] = zb0.y; Bf0[boff + 4] = zb0.z; Bf0[boff + 6] = zb0.w;
            Bf1[boff] = zb1.x; Bf1[boff + 2] = zb1.y; Bf1[boff + 4] = zb1.z; Bf1[boff + 6] = zb1.w;
        }
        __syncthreads();   // bits + frags visible

        // ---- two phases (diag pairs: phase 1 redundant but idempotent) ----
#pragma unroll 1
        for (int t = 0; t < 2; t++) {
            const int rb = t ? b1c : b0c;
            const int cb = t ? b0c : b1c;
            const int RG = rb * 128, CG = cb * 128;
            const uint32_t* Asm32 = (const uint32_t*)(smem + OFF_AF + t * 8192);
            const uint32_t* Bsm32 = (const uint32_t*)(smem + OFF_BF + t * 8192);

            float acc[2][4][4];
#pragma unroll
            for (int mt = 0; mt < 2; mt++)
#pragma unroll
                for (int nt = 0; nt < 4; nt++)
#pragma unroll
                    for (int r = 0; r < 4; r++) acc[mt][nt][r] = 0.0f;

#pragma unroll
            for (int ks = 0; ks < 2; ks++) {
                uint4 a[2];
                uint2 b[4];
#pragma unroll
                for (int mt = 0; mt < 2; mt++)
                    a[mt] = *(const uint4*)(Asm32 + ((ks * 8 + wm * 2 + mt) * 32 + lane) * 4);
#pragma unroll
                for (int nt = 0; nt < 4; nt++)
                    b[nt] = *(const uint2*)(Bsm32 + ((ks * 16 + wn * 4 + nt) * 32 + lane) * 2);
#pragma unroll
                for (int mt = 0; mt < 2; mt++)
#pragma unroll
                    for (int nt = 0; nt < 4; nt++)
                        mma_fp8(acc[mt][nt], a[mt], b[nt]);
            }

            const unsigned* rowB = t ? Qbits : Pbits;
            const unsigned* colB = t ? Pbits : Qbits;

            unsigned cw[4][2];
#pragma unroll
            for (int nt = 0; nt < 4; nt++)
#pragma unroll
                for (int p = 0; p < 2; p++) {
                    int c = wn * 32 + nt * 8 + 2 * l4 + p;
                    cw[nt][p] = colB[c * 4 + wm];
                }

            float rs[4], rp2[4];
            float cs[4][2], cp2[4][2];
#pragma unroll
            for (int nt = 0; nt < 4; nt++) {
                cs[nt][0] = cs[nt][1] = 0.f;
                cp2[nt][0] = cp2[nt][1] = 0.f;
            }

#pragma unroll
            for (int mt = 0; mt < 2; mt++) {
#pragma unroll
                for (int half = 0; half < 2; half++) {
                    int bitidx = mt * 16 + q + 8 * half;      // row % 32
                    int r = wm * 32 + bitidx;
                    unsigned rw = rowB[r * 4 + wn];
                    float rsum = 0.f, rpos = 0.f;
#pragma unroll
                    for (int nt = 0; nt < 4; nt++) {
                        float v0 = exp_tau(acc[mt][nt][half * 2 + 0]);
                        float v1 = exp_tau(acc[mt][nt][half * 2 + 1]);
                        unsigned rbits = rw >> (nt * 8 + 2 * l4);
                        rsum += v0 + v1;
                        if (rbits & 1u) rpos += v0;
                        if (rbits & 2u) rpos += v1;
                        cs[nt][0] += v0;
                        cs[nt][1] += v1;
                        if ((cw[nt][0] >> bitidx) & 1u) cp2[nt][0] += v0;
                        if ((cw[nt][1] >> bitidx) & 1u) cp2[nt][1] += v1;
                    }
                    rsum += __shfl_xor_sync(0xFFFFFFFF, rsum, 1);
                    rsum += __shfl_xor_sync(0xFFFFFFFF, rsum, 2);
                    rpos += __shfl_xor_sync(0xFFFFFFFF, rpos, 1);
                    rpos += __shfl_xor_sync(0xFFFFFFFF, rpos, 2);
                    rs[mt * 2 + half] = rsum;
                    rp2[mt * 2 + half] = rpos;
                }
            }
#pragma unroll
            for (int nt = 0; nt < 4; nt++)
#pragma unroll
                for (int p = 0; p < 2; p++) {
                    float v = cs[nt][p];
                    v += __shfl_xor_sync(0xFFFFFFFF, v, 4);
                    v += __shfl_xor_sync(0xFFFFFFFF, v, 8);
                    v += __shfl_xor_sync(0xFFFFFFFF, v, 16);
                    cs[nt][p] = v;
                    float w = cp2[nt][p];
                    w += __shfl_xor_sync(0xFFFFFFFF, w, 4);
                    w += __shfl_xor_sync(0xFFFFFFFF, w, 8);
                    w += __shfl_xor_sync(0xFFFFFFFF, w, 16);
                    cp2[nt][p] = w;
                }

            __syncthreads();   // prior reds consumers done

            if (l4 == 0) {
#pragma unroll
                for (int mt = 0; mt < 2; mt++)
#pragma unroll
                    for (int half = 0; half < 2; half++) {
                        int r = wm * 32 + mt * 16 + q + 8 * half;
                        RedRowS[r * 4 + wn] = rs[mt * 2 + half];
                        RedRowP[r * 4 + wn] = rp2[mt * 2 + half];
                    }
            }
            if (lane < 4) {
#pragma unroll
                for (int nt = 0; nt < 4; nt++)
#pragma unroll
                    for (int p = 0; p < 2; p++) {
                        int c = wn * 32 + nt * 8 + 2 * lane + p;
                        RedColS[c * 4 + wm] = cs[nt][p];
                        RedColP[c * 4 + wm] = cp2[nt][p];
                    }
            }
            __syncthreads();

            if (tid < 128) {
                float s = RedRowS[tid * 4 + 0] + RedRowS[tid * 4 + 1] +
                          RedRowS[tid * 4 + 2] + RedRowS[tid * 4 + 3];
                float sp = RedRowP[tid * 4 + 0] + RedRowP[tid * 4 + 1] +
                           RedRowP[tid * 4 + 2] + RedRowP[tid * 4 + 3];
                g_prow_sum[cb][RG + tid] = s;
                g_prow_pos[cb][RG + tid] = sp;
                float cc = RedColS[tid * 4 + 0] + RedColS[tid * 4 + 1] +
                           RedColS[tid * 4 + 2] + RedColS[tid * 4 + 3];
                float cp = RedColP[tid * 4 + 0] + RedColP[tid * 4 + 1] +
                           RedColP[tid * 4 + 2] + RedColP[tid * 4 + 3];
                g_pcol_sum[rb][CG + tid] = cc;
                g_pcol_pos[rb][CG + tid] = cp;
            }
            __syncthreads();   // finalize reads done before next writes
        }

        // advance pair window
        b0c = b0n; b1c = b1n;
        decode_pair(bid + (i + 2) * NSM, b0n, b1n);
    }
}

// ---------------- kernel 3: parallel partial reduce + log terms ----------------
__global__ void reduce_kernel() {
    __shared__ float red[4][8][32];
    int lane = threadIdx.x & 31, w = threadIdx.x >> 5;
    int i = blockIdx.x * 32 + lane;
    float rs = 0.f, rp = 0.f, cs = 0.f, cp = 0.f;
#pragma unroll
    for (int j = 0; j < 8; j++) {
        int t = w * 8 + j;
        rs += g_prow_sum[t][i];
        rp += g_prow_pos[t][i];
        cs += g_pcol_sum[t][i];
        cp += g_pcol_pos[t][i];
    }
    red[0][w][lane] = rs;
    red[1][w][lane] = rp;
    red[2][w][lane] = cs;
    red[3][w][lane] = cp;
    __syncthreads();
    if (w == 0) {
        float trs = 0.f, trp = 0.f, tcs = 0.f, tcp = 0.f;
#pragma unroll
        for (int k = 0; k < 8; k++) {
            trs += red[0][k][lane];
            trp += red[1][k][lane];
            tcs += red[2][k][lane];
            tcp += red[3][k][lane];
        }
        float contrib = LAM * (logf(trp) - logf(trs + EPS)) +
                        (1.0f - LAM) * (logf(tcp) - logf(tcs + EPS));
#pragma unroll
        for (int off = 16; off > 0; off >>= 1)
            contrib += __shfl_xor_sync(0xFFFFFFFF, contrib, off);
        if (lane == 0) g_blocksum[blockIdx.x] = contrib;
    }
}

__global__ void final_kernel(float* __restrict__ out) {
    int tid = threadIdx.x;
    float v = g_blocksum[tid];
#pragma unroll
    for (int off = 16; off > 0; off >>= 1)
        v += __shfl_xor_sync(0xFFFFFFFF, v, off);
    __shared__ float ws[8];
    int lane = tid & 31, warp = tid >> 5;
    if (lane == 0) ws[warp] = v;
    __syncthreads();
    if (warp == 0) {
        float s = (lane < 8) ? ws[lane] : 0.0f;
#pragma unroll
        for (int off = 4; off > 0; off >>= 1)
            s += __shfl_xor_sync(0xFFFFFFFF, s, off);
        if (lane == 0) out[0] = -s * (1.0f / (float)N);
    }
}

// ---------------- launch ----------------
extern "C" void kernel_launch(void* const* d_in, const int* in_sizes, int n_in,
                              void* d_out, int out_size) {
    const float* z_mp = (const float*)d_in[0];
    const float* z_sc = (const float*)d_in[1];
    const int* pos = (const int*)d_in[2];
    float* out = (float*)d_out;

    cudaFuncSetAttribute(pair_kernel, cudaFuncAttributeMaxDynamicSharedMemorySize,
                         SMEM_BYTES);

    normalize_kernel<<<2 * N / 8, 256>>>(z_mp, z_sc);
    pair_kernel<<<NSM, 512, SMEM_BYTES>>>(pos);
    reduce_kernel<<<256, 256>>>();
    final_kernel<<<1, 256>>>(out);
}

// round 15
// speedup vs baseline: 1.1185x; 1.1185x over previous
#include <cuda_runtime.h>
#include <cuda_bf16.h>
#include <cstdint>
#include <stdint.h>
#include <math.h>

#define N 8192
#define D 64
#define LAM 0.5f
#define EPS 1e-8f
#define NT 64
#define NPAIRS 2080

// ---------------- device scratch ----------------
__device__ uint16_t g_zn_mp[N * 32];   // e4m3-packed normalized rows (64 B/row)
__device__ uint16_t g_zn_sc[N * 32];
__device__ float g_prow_sum[NT][N];
__device__ float g_prow_pos[NT][N];
__device__ float g_pcol_sum[NT][N];
__device__ float g_pcol_pos[NT][N];
__device__ float g_blocksum[256];

// smem layout (dynamic)
#define OFF_AF   0            // A frags, 2 phases x 8192
#define OFF_BF   16384        // B frags, 2 phases x 8192
#define OFF_PB   32768        // P bits 2048
#define OFF_QB   34816        // Q bits 2048
#define OFF_RING 36864        // 4 slots x 8192 raw pos
#define SMEM_BYTES 69632
// reduction overlay on ring slot 0 (pos fully consumed by then)
#define OFF_RRS  OFF_RING
#define OFF_RRP  (OFF_RING + 2048)
#define OFF_RCS  (OFF_RING + 4096)
#define OFF_RCP  (OFF_RING + 5120)

__device__ __forceinline__ float exp_tau(float x) {
    float y = x * 1.80336880f;   // (1/0.8) * log2(e)
    float r;
    asm("ex2.approx.ftz.f32 %0, %1;" : "=f"(r) : "f"(y));
    return r;
}

__device__ __forceinline__ void mma_fp8(float* c, const uint4& a, const uint2& b) {
    asm volatile(
        "mma.sync.aligned.m16n8k32.row.col.f32.e4m3.e4m3.f32 "
        "{%0,%1,%2,%3}, {%4,%5,%6,%7}, {%8,%9}, {%0,%1,%2,%3};"
        : "+f"(c[0]), "+f"(c[1]), "+f"(c[2]), "+f"(c[3])
        : "r"(a.x), "r"(a.y), "r"(a.z), "r"(a.w), "r"(b.x), "r"(b.y));
}

__device__ __forceinline__ uint32_t smem_u32(const void* p) {
    uint32_t a;
    asm("{ .reg .u64 t; cvta.to.shared.u64 t, %1; cvt.u32.u64 %0, t; }"
        : "=r"(a) : "l"(p));
    return a;
}

// ---------------- kernel 1: normalize + quantize to e4m3 ----------------
__global__ void normalize_kernel(const float* __restrict__ zmp,
                                 const float* __restrict__ zsc) {
    int gwarp = (blockIdx.x * blockDim.x + threadIdx.x) >> 5;
    int lane = threadIdx.x & 31;
    const float* src;
    uint16_t* dst;
    if (gwarp < N) {
        src = zmp + (size_t)gwarp * D;
        dst = g_zn_mp + (size_t)gwarp * 32;
    } else {
        src = zsc + (size_t)(gwarp - N) * D;
        dst = g_zn_sc + (size_t)(gwarp - N) * 32;
    }
    float2 v = *(const float2*)(src + 2 * lane);
    float s = v.x * v.x + v.y * v.y;
#pragma unroll
    for (int off = 16; off > 0; off >>= 1)
        s += __shfl_xor_sync(0xFFFFFFFF, s, off);
    float inv = rsqrtf(s);
    uint16_t packed;
    asm("cvt.rn.satfinite.e4m3x2.f32 %0, %1, %2;"
        : "=h"(packed) : "f"(v.y * inv), "f"(v.x * inv));
    dst[lane] = packed;
}

// issue one 8KB pos chunk (16 rows x 512B) via cp.async; 2 x 16B segs per thread
// chunk c in [0,16): o = c>>3 (0=P,1=Q), rows [(c&7)*16, +16)
__device__ __forceinline__ void issue_chunk(uint32_t sb, const int* __restrict__ pos,
                                            int c, int b0, int b1) {
    int o = c >> 3;
    int rb = o ? b1 : b0;
    int cb = o ? b0 : b1;
#pragma unroll
    for (int k = 0; k < 2; k++) {
        int s = threadIdx.x * 2 + k;              // 0..511
        int row = (c & 7) * 16 + (s >> 5);
        const int* src = pos + (size_t)(rb * 128 + row) * N + cb * 128 + (s & 31) * 4;
        uint32_t dst = sb + OFF_RING + (uint32_t)(c & 3) * 8192u + (uint32_t)s * 16u;
        asm volatile("cp.async.cg.shared.global [%0], [%1], 16;" :: "r"(dst), "l"(src));
    }
    asm volatile("cp.async.commit_group;" ::: "memory");
}

// ---------------- kernel 2: symmetric-pair tile kernel (fp8 HMMA) ----------------
__global__ __launch_bounds__(256, 2)
void pair_kernel(const int* __restrict__ pos) {
    extern __shared__ char smem[];
    const uint32_t sb = smem_u32(smem);
    unsigned* Pbits = (unsigned*)(smem + OFF_PB);
    unsigned* Qbits = (unsigned*)(smem + OFF_QB);
    float* RedRowS = (float*)(smem + OFF_RRS);   // [128][4]
    float* RedRowP = (float*)(smem + OFF_RRP);
    float* RedColS = (float*)(smem + OFF_RCS);   // [128][2]
    float* RedColP = (float*)(smem + OFF_RCP);

    const int tid = threadIdx.x;
    const int lane = tid & 31;
    const int wid = tid >> 5;
    const int wm = wid >> 2;   // 0..1 : 64-row slab
    const int wn = wid & 3;    // 0..3 : 32-col slab
    const int q = lane >> 2, l4 = lane & 3;

    // triangular decode
    int b0 = 0, rem = blockIdx.x;
    while (rem >= NT - b0) { rem -= NT - b0; b0++; }
    int b1 = b0 + rem;

    // ==== head: prologue cp.async chunks, then z stage under the stream ====
#pragma unroll
    for (int c = 0; c < 4; c++) issue_chunk(sb, pos, c, b0, b1);

    // z: all 4 tiles (2 phases) -> registers -> frag smem
    {
        const int m = tid >> 1, hc = (tid & 1) * 2;   // 2 uint4 per tile per thread
        const char* A0g = (const char*)g_zn_mp + (size_t)(b0 * 128) * 64;
        const char* B0g = (const char*)g_zn_sc + (size_t)(b1 * 128) * 64;
        const char* A1g = (const char*)g_zn_mp + (size_t)(b1 * 128) * 64;
        const char* B1g = (const char*)g_zn_sc + (size_t)(b0 * 128) * 64;
        uint4 za0[2], zb0[2], za1[2], zb1[2];
#pragma unroll
        for (int i = 0; i < 2; i++) {
            za0[i] = *(const uint4*)(A0g + m * 64 + (hc + i) * 16);
            zb0[i] = *(const uint4*)(B0g + m * 64 + (hc + i) * 16);
            za1[i] = *(const uint4*)(A1g + m * 64 + (hc + i) * 16);
            zb1[i] = *(const uint4*)(B1g + m * 64 + (hc + i) * 16);
        }
#pragma unroll
        for (int i = 0; i < 2; i++) {
            int c4 = hc + i;
            int ks = c4 >> 1, kh = c4 & 1;
            int aoff = ((ks * 8 + (m >> 4)) * 32 + (m & 7) * 4) * 4 + ((m >> 3) & 1) + 2 * kh;
            int boff = ((ks * 16 + (m >> 3)) * 32 + (m & 7) * 4) * 2 + kh;
            uint32_t* Af0 = (uint32_t*)(smem + OFF_AF);
            uint32_t* Af1 = (uint32_t*)(smem + OFF_AF + 8192);
            uint32_t* Bf0 = (uint32_t*)(smem + OFF_BF);
            uint32_t* Bf1 = (uint32_t*)(smem + OFF_BF + 8192);
            Af0[aoff] = za0[i].x; Af0[aoff + 4] = za0[i].y; Af0[aoff + 8] = za0[i].z; Af0[aoff + 12] = za0[i].w;
            Af1[aoff] = za1[i].x; Af1[aoff + 4] = za1[i].y; Af1[aoff + 8] = za1[i].z; Af1[aoff + 12] = za1[i].w;
            Bf0[boff] = zb0[i].x; Bf0[boff + 2] = zb0[i].y; Bf0[boff + 4] = zb0[i].z; Bf0[boff + 6] = zb0[i].w;
            Bf1[boff] = zb1[i].x; Bf1[boff + 2] = zb1[i].y; Bf1[boff + 4] = zb1[i].z; Bf1[boff + 6] = zb1[i].w;
        }
    }

    // ==== pos pack pipeline: 16 chunks, depth-4 ring ====
    const int sh = (lane & 7) * 4;
#pragma unroll
    for (int c = 0; c < 16; c++) {
        if (c <= 12) { asm volatile("cp.async.wait_group 3;" ::: "memory"); }
        else if (c == 13) { asm volatile("cp.async.wait_group 2;" ::: "memory"); }
        else if (c == 14) { asm volatile("cp.async.wait_group 1;" ::: "memory"); }
        else { asm volatile("cp.async.wait_group 0;" ::: "memory"); }
        __syncthreads();   // chunk c visible to all threads
        unsigned* bits = (c >> 3) ? Qbits : Pbits;
#pragma unroll
        for (int j = 0; j < 2; j++) {
            int ric = wid + j * 8;             // row in chunk 0..15
            uint4 v = *(const uint4*)(smem + OFF_RING + (c & 3) * 8192 + ric * 512 + lane * 16);
            unsigned w = (unsigned)((v.x & 1) | ((v.y & 1) << 1) | ((v.z & 1) << 2) |
                                    ((v.w & 1) << 3)) << sh;
            w |= __shfl_xor_sync(0xFFFFFFFF, w, 1);
            w |= __shfl_xor_sync(0xFFFFFFFF, w, 2);
            w |= __shfl_xor_sync(0xFFFFFFFF, w, 4);
            if ((lane & 7) == 0) {
                int grow = (c & 7) * 16 + ric;
                bits[grow * 4 + (lane >> 3)] = w;
            }
        }
        __syncthreads();   // all reads of slot c&3 done before reuse
        if (c < 12) issue_chunk(sb, pos, c + 4, b0, b1);
    }
    __syncthreads();   // last bits visible; frags long since synced

    const int nphase = (b0 == b1) ? 1 : 2;

    for (int t = 0; t < nphase; t++) {
        const int rb = t ? b1 : b0;
        const int cb = t ? b0 : b1;
        const int RG = rb * 128, CG = cb * 128;
        const uint32_t* Asm32 = (const uint32_t*)(smem + OFF_AF + t * 8192);
        const uint32_t* Bsm32 = (const uint32_t*)(smem + OFF_BF + t * 8192);

        if (t == 1) __syncthreads();   // phase-0 finalize reads of reds done

        // ---- fp8 tensor-core mainloop: warp tile 64x32, 2 K-steps of 32 ----
        float acc[4][4][4];
#pragma unroll
        for (int mt = 0; mt < 4; mt++)
#pragma unroll
            for (int nt = 0; nt < 4; nt++)
#pragma unroll
                for (int r = 0; r < 4; r++) acc[mt][nt][r] = 0.0f;

#pragma unroll
        for (int ks = 0; ks < 2; ks++) {
            uint4 a[4];
            uint2 b[4];
#pragma unroll
            for (int mt = 0; mt < 4; mt++)
                a[mt] = *(const uint4*)(Asm32 + ((ks * 8 + wm * 4 + mt) * 32 + lane) * 4);
#pragma unroll
            for (int nt = 0; nt < 4; nt++)
                b[nt] = *(const uint2*)(Bsm32 + ((ks * 16 + wn * 4 + nt) * 32 + lane) * 2);
#pragma unroll
            for (int mt = 0; mt < 4; mt++)
#pragma unroll
                for (int nt = 0; nt < 4; nt++)
                    mma_fp8(acc[mt][nt], a[mt], b[nt]);
        }

        // ---- epilogue: MUFU exp + bitmask pos pairing + partial reductions ----
        const unsigned* rowB = t ? Qbits : Pbits;
        const unsigned* colB = t ? Pbits : Qbits;

        unsigned cw[4][2][2];
#pragma unroll
        for (int nt = 0; nt < 4; nt++)
#pragma unroll
            for (int p = 0; p < 2; p++) {
                int c = wn * 32 + nt * 8 + 2 * l4 + p;
#pragma unroll
                for (int ws = 0; ws < 2; ws++)
                    cw[nt][p][ws] = colB[c * 4 + wm * 2 + ws];
            }

        float rs[8], rp2[8];
        float cs[4][2], cp2[4][2];
#pragma unroll
        for (int nt = 0; nt < 4; nt++) { cs[nt][0] = cs[nt][1] = 0.f; cp2[nt][0] = cp2[nt][1] = 0.f; }

#pragma unroll
        for (int mt = 0; mt < 4; mt++) {
            const int wsel = (mt >= 2) ? 1 : 0;
#pragma unroll
            for (int half = 0; half < 2; half++) {
                int rloc = mt * 16 + q + 8 * half;
                int r = wm * 64 + rloc;
                int bitidx = (mt & 1) * 16 + q + 8 * half;
                unsigned rw = rowB[r * 4 + wn];
                float rsum = 0.f, rpos = 0.f;
#pragma unroll
                for (int nt = 0; nt < 4; nt++) {
                    float v0 = exp_tau(acc[mt][nt][half * 2 + 0]);
                    float v1 = exp_tau(acc[mt][nt][half * 2 + 1]);
                    unsigned rbits = rw >> (nt * 8 + 2 * l4);
                    rsum += v0 + v1;
                    if (rbits & 1u) rpos += v0;
                    if (rbits & 2u) rpos += v1;
                    cs[nt][0] += v0;
                    cs[nt][1] += v1;
                    if ((cw[nt][0][wsel] >> bitidx) & 1u) cp2[nt][0] += v0;
                    if ((cw[nt][1][wsel] >> bitidx) & 1u) cp2[nt][1] += v1;
                }
                rsum += __shfl_xor_sync(0xFFFFFFFF, rsum, 1);
                rsum += __shfl_xor_sync(0xFFFFFFFF, rsum, 2);
                rpos += __shfl_xor_sync(0xFFFFFFFF, rpos, 1);
                rpos += __shfl_xor_sync(0xFFFFFFFF, rpos, 2);
                rs[mt * 2 + half] = rsum;
                rp2[mt * 2 + half] = rpos;
            }
        }
#pragma unroll
        for (int nt = 0; nt < 4; nt++)
#pragma unroll
            for (int p = 0; p < 2; p++) {
                float v = cs[nt][p];
                v += __shfl_xor_sync(0xFFFFFFFF, v, 4);
                v += __shfl_xor_sync(0xFFFFFFFF, v, 8);
                v += __shfl_xor_sync(0xFFFFFFFF, v, 16);
                cs[nt][p] = v;
                float w = cp2[nt][p];
                w += __shfl_xor_sync(0xFFFFFFFF, w, 4);
                w += __shfl_xor_sync(0xFFFFFFFF, w, 8);
                w += __shfl_xor_sync(0xFFFFFFFF, w, 16);
                cp2[nt][p] = w;
            }

        __syncthreads();   // safe to (re)use reds overlay

        if (l4 == 0) {
#pragma unroll
            for (int mt = 0; mt < 4; mt++)
#pragma unroll
                for (int half = 0; half < 2; half++) {
                    int r = wm * 64 + mt * 16 + q + 8 * half;
                    RedRowS[r * 4 + wn] = rs[mt * 2 + half];
                    RedRowP[r * 4 + wn] = rp2[mt * 2 + half];
                }
        }
        if (lane < 4) {
#pragma unroll
            for (int nt = 0; nt < 4; nt++)
#pragma unroll
                for (int p = 0; p < 2; p++) {
                    int c = wn * 32 + nt * 8 + 2 * lane + p;
                    RedColS[c * 2 + wm] = cs[nt][p];
                    RedColP[c * 2 + wm] = cp2[nt][p];
                }
        }
        __syncthreads();

        if (tid < 128) {
            float s = RedRowS[tid * 4 + 0] + RedRowS[tid * 4 + 1] +
                      RedRowS[tid * 4 + 2] + RedRowS[tid * 4 + 3];
            float sp = RedRowP[tid * 4 + 0] + RedRowP[tid * 4 + 1] +
                       RedRowP[tid * 4 + 2] + RedRowP[tid * 4 + 3];
            g_prow_sum[cb][RG + tid] = s;
            g_prow_pos[cb][RG + tid] = sp;
            float c = RedColS[tid * 2 + 0] + RedColS[tid * 2 + 1];
            float cp = RedColP[tid * 2 + 0] + RedColP[tid * 2 + 1];
            g_pcol_sum[rb][CG + tid] = c;
            g_pcol_pos[rb][CG + tid] = cp;
        }
    }
}

// ---------------- kernel 3: parallel partial reduce + log terms ----------------
__global__ void reduce_kernel() {
    __shared__ float red[4][8][32];
    int lane = threadIdx.x & 31, w = threadIdx.x >> 5;
    int i = blockIdx.x * 32 + lane;
    float rs = 0.f, rp = 0.f, cs = 0.f, cp = 0.f;
#pragma unroll
    for (int j = 0; j < 8; j++) {
        int t = w * 8 + j;
        rs += g_prow_sum[t][i];
        rp += g_prow_pos[t][i];
        cs += g_pcol_sum[t][i];
        cp += g_pcol_pos[t][i];
    }
    red[0][w][lane] = rs;
    red[1][w][lane] = rp;
    red[2][w][lane] = cs;
    red[3][w][lane] = cp;
    __syncthreads();
    if (w == 0) {
        float trs = 0.f, trp = 0.f, tcs = 0.f, tcp = 0.f;
#pragma unroll
        for (int k = 0; k < 8; k++) {
            trs += red[0][k][lane];
            trp += red[1][k][lane];
            tcs += red[2][k][lane];
            tcp += red[3][k][lane];
        }
        float contrib = LAM * (logf(trp) - logf(trs + EPS)) +
                        (1.0f - LAM) * (logf(tcp) - logf(tcs + EPS));
#pragma unroll
        for (int off = 16; off > 0; off >>= 1)
            contrib += __shfl_xor_sync(0xFFFFFFFF, contrib, off);
        if (lane == 0) g_blocksum[blockIdx.x] = contrib;
    }
}

__global__ void final_kernel(float* __restrict__ out) {
    int tid = threadIdx.x;
    float v = g_blocksum[tid];
#pragma unroll
    for (int off = 16; off > 0; off >>= 1)
        v += __shfl_xor_sync(0xFFFFFFFF, v, off);
    __shared__ float ws[8];
    int lane = tid & 31, warp = tid >> 5;
    if (lane == 0) ws[warp] = v;
    __syncthreads();
    if (warp == 0) {
        float s = (lane < 8) ? ws[lane] : 0.0f;
#pragma unroll
        for (int off = 4; off > 0; off >>= 1)
            s += __shfl_xor_sync(0xFFFFFFFF, s, off);
        if (lane == 0) out[0] = -s * (1.0f / (float)N);
    }
}

// ---------------- launch ----------------
extern "C" void kernel_launch(void* const* d_in, const int* in_sizes, int n_in,
                              void* d_out, int out_size) {
    const float* z_mp = (const float*)d_in[0];
    const float* z_sc = (const float*)d_in[1];
    const int* pos = (const int*)d_in[2];
    float* out = (float*)d_out;

    cudaFuncSetAttribute(pair_kernel, cudaFuncAttributeMaxDynamicSharedMemorySize,
                         SMEM_BYTES);

    normalize_kernel<<<2 * N / 8, 256>>>(z_mp, z_sc);
    pair_kernel<<<NPAIRS, 256, SMEM_BYTES>>>(pos);
    reduce_kernel<<<256, 256>>>();
    final_kernel<<<1, 256>>>(out);
}

// round 16
// speedup vs baseline: 1.4555x; 1.3012x over previous
#include <cuda_runtime.h>
#include <cuda_bf16.h>
#include <cstdint>
#include <stdint.h>
#include <math.h>

#define N 8192
#define D 64
#define LAM 0.5f
#define EPS 1e-8f
#define NT 64
#define NPAIRS 2080

// ---------------- device scratch ----------------
__device__ uint16_t g_zn_mp[N * 32];   // e4m3-packed normalized rows (64 B/row)
__device__ uint16_t g_zn_sc[N * 32];
__device__ float g_prow_sum[NT][N];
__device__ float g_prow_pos[NT][N];
__device__ float g_pcol_sum[NT][N];
__device__ float g_pcol_pos[NT][N];
__device__ float g_blocksum[256];
__device__ int g_count;   // zero-init; reset by last block each launch

// smem layout (dynamic)
#define OFF_AF   0            // A frags, 2 phases x 8192
#define OFF_BF   16384        // B frags, 2 phases x 8192
#define OFF_PB   32768        // P bits 2048
#define OFF_QB   34816        // Q bits 2048
#define OFF_RRS  36864        // RedRowS [128][4] f32
#define OFF_RRP  38912
#define OFF_RCS  40960        // RedColS [128][2] f32
#define OFF_RCP  41984
#define SMEM_BYTES 43008

__device__ __forceinline__ float exp_tau(float x) {
    float y = x * 1.80336880f;   // (1/0.8) * log2(e)
    float r;
    asm("ex2.approx.ftz.f32 %0, %1;" : "=f"(r) : "f"(y));
    return r;
}

__device__ __forceinline__ void mma_fp8(float* c, const uint4& a, const uint2& b) {
    asm volatile(
        "mma.sync.aligned.m16n8k32.row.col.f32.e4m3.e4m3.f32 "
        "{%0,%1,%2,%3}, {%4,%5,%6,%7}, {%8,%9}, {%0,%1,%2,%3};"
        : "+f"(c[0]), "+f"(c[1]), "+f"(c[2]), "+f"(c[3])
        : "r"(a.x), "r"(a.y), "r"(a.z), "r"(a.w), "r"(b.x), "r"(b.y));
}

// ---------------- kernel 1: normalize + quantize to e4m3 ----------------
__global__ void normalize_kernel(const float* __restrict__ zmp,
                                 const float* __restrict__ zsc) {
    int gwarp = (blockIdx.x * blockDim.x + threadIdx.x) >> 5;
    int lane = threadIdx.x & 31;
    const float* src;
    uint16_t* dst;
    if (gwarp < N) {
        src = zmp + (size_t)gwarp * D;
        dst = g_zn_mp + (size_t)gwarp * 32;
    } else {
        src = zsc + (size_t)(gwarp - N) * D;
        dst = g_zn_sc + (size_t)(gwarp - N) * 32;
    }
    float2 v = *(const float2*)(src + 2 * lane);
    float s = v.x * v.x + v.y * v.y;
#pragma unroll
    for (int off = 16; off > 0; off >>= 1)
        s += __shfl_xor_sync(0xFFFFFFFF, s, off);
    float inv = rsqrtf(s);
    uint16_t packed;
    asm("cvt.rn.satfinite.e4m3x2.f32 %0, %1, %2;"
        : "=h"(packed) : "f"(v.y * inv), "f"(v.x * inv));
    dst[lane] = packed;
}

// ---------------- kernel 2: symmetric-pair tile kernel (fp8 HMMA) ----------------
__global__ __launch_bounds__(256, 2)
void pair_kernel(const int* __restrict__ pos) {
    extern __shared__ char smem[];
    unsigned* Pbits = (unsigned*)(smem + OFF_PB);
    unsigned* Qbits = (unsigned*)(smem + OFF_QB);
    float* RedRowS = (float*)(smem + OFF_RRS);   // [128][4]
    float* RedRowP = (float*)(smem + OFF_RRP);
    float* RedColS = (float*)(smem + OFF_RCS);   // [128][2]
    float* RedColP = (float*)(smem + OFF_RCP);

    const int tid = threadIdx.x;
    const int lane = tid & 31;
    const int wid = tid >> 5;
    const int wm = wid >> 2;   // 0..1 : 64-row slab
    const int wn = wid & 3;    // 0..3 : 32-col slab
    const int q = lane >> 2, l4 = lane & 3;

    // triangular decode: blockIdx.x -> (b0, b1), b0 <= b1
    int b0 = 0, rem = blockIdx.x;
    while (rem >= NT - b0) { rem -= NT - b0; b0++; }
    int b1 = b0 + rem;

    const int sh = (lane & 7) * 4;
    const int widx = lane >> 3;
    const int* Pbase = pos + (size_t)(b0 * 128 + wid) * N + b1 * 128 + lane * 4;
    const int* Qbase = pos + (size_t)(b1 * 128 + wid) * N + b0 * 128 + lane * 4;

    // ==== CTA head: z loads for BOTH phases issued first, pos batches overlap ====
    {
        const int m = tid >> 1, hc = (tid & 1) * 2;   // 2 uint4 per tile per thread
        const char* A0g = (const char*)g_zn_mp + (size_t)(b0 * 128) * 64;
        const char* B0g = (const char*)g_zn_sc + (size_t)(b1 * 128) * 64;
        const char* A1g = (const char*)g_zn_mp + (size_t)(b1 * 128) * 64;
        const char* B1g = (const char*)g_zn_sc + (size_t)(b0 * 128) * 64;
        uint4 za0[2], zb0[2], za1[2], zb1[2];
#pragma unroll
        for (int i = 0; i < 2; i++) {
            za0[i] = *(const uint4*)(A0g + m * 64 + (hc + i) * 16);
            zb0[i] = *(const uint4*)(B0g + m * 64 + (hc + i) * 16);
            za1[i] = *(const uint4*)(A1g + m * 64 + (hc + i) * 16);
            zb1[i] = *(const uint4*)(B1g + m * 64 + (hc + i) * 16);
        }

        int4 pb[8], qb[8];
        // pos batch 1: 16 independent streaming LDG.128 in flight
#pragma unroll
        for (int j = 0; j < 8; j++) {
            pb[j] = __ldcs((const int4*)(Pbase + (size_t)j * 8 * N));
            qb[j] = __ldcs((const int4*)(Qbase + (size_t)j * 8 * N));
        }

        // store all 4 z tiles to frag smem (consumes z regs; pos still in flight)
#pragma unroll
        for (int i = 0; i < 2; i++) {
            int c4 = hc + i;
            int ks = c4 >> 1, kh = c4 & 1;
            int aoff = ((ks * 8 + (m >> 4)) * 32 + (m & 7) * 4) * 4 + ((m >> 3) & 1) + 2 * kh;
            int boff = ((ks * 16 + (m >> 3)) * 32 + (m & 7) * 4) * 2 + kh;
            uint32_t* Af0 = (uint32_t*)(smem + OFF_AF);
            uint32_t* Af1 = (uint32_t*)(smem + OFF_AF + 8192);
            uint32_t* Bf0 = (uint32_t*)(smem + OFF_BF);
            uint32_t* Bf1 = (uint32_t*)(smem + OFF_BF + 8192);
            Af0[aoff] = za0[i].x; Af0[aoff + 4] = za0[i].y; Af0[aoff + 8] = za0[i].z; Af0[aoff + 12] = za0[i].w;
            Af1[aoff] = za1[i].x; Af1[aoff + 4] = za1[i].y; Af1[aoff + 8] = za1[i].z; Af1[aoff + 12] = za1[i].w;
            Bf0[boff] = zb0[i].x; Bf0[boff + 2] = zb0[i].y; Bf0[boff + 4] = zb0[i].z; Bf0[boff + 6] = zb0[i].w;
            Bf1[boff] = zb1[i].x; Bf1[boff + 2] = zb1[i].y; Bf1[boff + 4] = zb1[i].z; Bf1[boff + 6] = zb1[i].w;
        }

        // pack+store pos batch 1
#pragma unroll
        for (int j = 0; j < 8; j++) {
            int r = wid + j * 8;
            unsigned pw = ((pb[j].x & 1) | ((pb[j].y & 1) << 1) | ((pb[j].z & 1) << 2) |
                           ((pb[j].w & 1) << 3)) << sh;
            unsigned qw = ((qb[j].x & 1) | ((qb[j].y & 1) << 1) | ((qb[j].z & 1) << 2) |
                           ((qb[j].w & 1) << 3)) << sh;
            pw |= __shfl_xor_sync(0xFFFFFFFF, pw, 1);
            pw |= __shfl_xor_sync(0xFFFFFFFF, pw, 2);
            pw |= __shfl_xor_sync(0xFFFFFFFF, pw, 4);
            qw |= __shfl_xor_sync(0xFFFFFFFF, qw, 1);
            qw |= __shfl_xor_sync(0xFFFFFFFF, qw, 2);
            qw |= __shfl_xor_sync(0xFFFFFFFF, qw, 4);
            if ((lane & 7) == 0) {
                Pbits[r * 4 + widx] = pw;
                Qbits[r * 4 + widx] = qw;
            }
        }
        // pos batch 2
#pragma unroll
        for (int j = 0; j < 8; j++) {
            pb[j] = __ldcs((const int4*)(Pbase + (size_t)(j + 8) * 8 * N));
            qb[j] = __ldcs((const int4*)(Qbase + (size_t)(j + 8) * 8 * N));
        }
#pragma unroll
        for (int j = 0; j < 8; j++) {
            int r = wid + (j + 8) * 8;
            unsigned pw = ((pb[j].x & 1) | ((pb[j].y & 1) << 1) | ((pb[j].z & 1) << 2) |
                           ((pb[j].w & 1) << 3)) << sh;
            unsigned qw = ((qb[j].x & 1) | ((qb[j].y & 1) << 1) | ((qb[j].z & 1) << 2) |
                           ((qb[j].w & 1) << 3)) << sh;
            pw |= __shfl_xor_sync(0xFFFFFFFF, pw, 1);
            pw |= __shfl_xor_sync(0xFFFFFFFF, pw, 2);
            pw |= __shfl_xor_sync(0xFFFFFFFF, pw, 4);
            qw |= __shfl_xor_sync(0xFFFFFFFF, qw, 1);
            qw |= __shfl_xor_sync(0xFFFFFFFF, qw, 2);
            qw |= __shfl_xor_sync(0xFFFFFFFF, qw, 4);
            if ((lane & 7) == 0) {
                Pbits[r * 4 + widx] = pw;
                Qbits[r * 4 + widx] = qw;
            }
        }
    }
    __syncthreads();   // all frags + pos bits visible

    const int nphase = (b0 == b1) ? 1 : 2;

    for (int t = 0; t < nphase; t++) {
        const int rb = t ? b1 : b0;
        const int cb = t ? b0 : b1;
        const int RG = rb * 128, CG = cb * 128;
        const uint32_t* Asm32 = (const uint32_t*)(smem + OFF_AF + t * 8192);
        const uint32_t* Bsm32 = (const uint32_t*)(smem + OFF_BF + t * 8192);

        if (t == 1) __syncthreads();   // phase-0 finalize reads of reds done

        // ---- fp8 tensor-core mainloop: warp tile 64x32, 2 K-steps of 32 ----
        float acc[4][4][4];
#pragma unroll
        for (int mt = 0; mt < 4; mt++)
#pragma unroll
            for (int nt = 0; nt < 4; nt++)
#pragma unroll
                for (int r = 0; r < 4; r++) acc[mt][nt][r] = 0.0f;

#pragma unroll
        for (int ks = 0; ks < 2; ks++) {
            uint4 a[4];
            uint2 b[4];
#pragma unroll
            for (int mt = 0; mt < 4; mt++)
                a[mt] = *(const uint4*)(Asm32 + ((ks * 8 + wm * 4 + mt) * 32 + lane) * 4);
#pragma unroll
            for (int nt = 0; nt < 4; nt++)
                b[nt] = *(const uint2*)(Bsm32 + ((ks * 16 + wn * 4 + nt) * 32 + lane) * 2);
#pragma unroll
            for (int mt = 0; mt < 4; mt++)
#pragma unroll
                for (int nt = 0; nt < 4; nt++)
                    mma_fp8(acc[mt][nt], a[mt], b[nt]);
        }

        // ---- epilogue: MUFU exp + bitmask pos pairing + partial reductions ----
        const unsigned* rowB = t ? Qbits : Pbits;
        const unsigned* colB = t ? Pbits : Qbits;

        unsigned cw[4][2][2];
#pragma unroll
        for (int nt = 0; nt < 4; nt++)
#pragma unroll
            for (int p = 0; p < 2; p++) {
                int c = wn * 32 + nt * 8 + 2 * l4 + p;
#pragma unroll
                for (int ws = 0; ws < 2; ws++)
                    cw[nt][p][ws] = colB[c * 4 + wm * 2 + ws];
            }

        float rs[8], rp2[8];
        float cs[4][2], cp2[4][2];
#pragma unroll
        for (int nt = 0; nt < 4; nt++) { cs[nt][0] = cs[nt][1] = 0.f; cp2[nt][0] = cp2[nt][1] = 0.f; }

#pragma unroll
        for (int mt = 0; mt < 4; mt++) {
            const int wsel = (mt >= 2) ? 1 : 0;
#pragma unroll
            for (int half = 0; half < 2; half++) {
                int rloc = mt * 16 + q + 8 * half;
                int r = wm * 64 + rloc;
                int bitidx = (mt & 1) * 16 + q + 8 * half;
                unsigned rw = rowB[r * 4 + wn];
                float rsum = 0.f, rpos = 0.f;
#pragma unroll
                for (int nt = 0; nt < 4; nt++) {
                    float v0 = exp_tau(acc[mt][nt][half * 2 + 0]);
                    float v1 = exp_tau(acc[mt][nt][half * 2 + 1]);
                    unsigned rbits = rw >> (nt * 8 + 2 * l4);
                    rsum += v0 + v1;
                    if (rbits & 1u) rpos += v0;
                    if (rbits & 2u) rpos += v1;
                    cs[nt][0] += v0;
                    cs[nt][1] += v1;
                    if ((cw[nt][0][wsel] >> bitidx) & 1u) cp2[nt][0] += v0;
                    if ((cw[nt][1][wsel] >> bitidx) & 1u) cp2[nt][1] += v1;
                }
                rsum += __shfl_xor_sync(0xFFFFFFFF, rsum, 1);
                rsum += __shfl_xor_sync(0xFFFFFFFF, rsum, 2);
                rpos += __shfl_xor_sync(0xFFFFFFFF, rpos, 1);
                rpos += __shfl_xor_sync(0xFFFFFFFF, rpos, 2);
                rs[mt * 2 + half] = rsum;
                rp2[mt * 2 + half] = rpos;
            }
        }
#pragma unroll
        for (int nt = 0; nt < 4; nt++)
#pragma unroll
            for (int p = 0; p < 2; p++) {
                float v = cs[nt][p];
                v += __shfl_xor_sync(0xFFFFFFFF, v, 4);
                v += __shfl_xor_sync(0xFFFFFFFF, v, 8);
                v += __shfl_xor_sync(0xFFFFFFFF, v, 16);
                cs[nt][p] = v;
                float w = cp2[nt][p];
                w += __shfl_xor_sync(0xFFFFFFFF, w, 4);
                w += __shfl_xor_sync(0xFFFFFFFF, w, 8);
                w += __shfl_xor_sync(0xFFFFFFFF, w, 16);
                cp2[nt][p] = w;
            }

        // dedicated reds smem: no pre-write barrier needed
        if (l4 == 0) {
#pragma unroll
            for (int mt = 0; mt < 4; mt++)
#pragma unroll
                for (int half = 0; half < 2; half++) {
                    int r = wm * 64 + mt * 16 + q + 8 * half;
                    RedRowS[r * 4 + wn] = rs[mt * 2 + half];
                    RedRowP[r * 4 + wn] = rp2[mt * 2 + half];
                }
        }
        if (lane < 4) {
#pragma unroll
            for (int nt = 0; nt < 4; nt++)
#pragma unroll
                for (int p = 0; p < 2; p++) {
                    int c = wn * 32 + nt * 8 + 2 * lane + p;
                    RedColS[c * 2 + wm] = cs[nt][p];
                    RedColP[c * 2 + wm] = cp2[nt][p];
                }
        }
        __syncthreads();

        if (tid < 128) {
            float s = RedRowS[tid * 4 + 0] + RedRowS[tid * 4 + 1] +
                      RedRowS[tid * 4 + 2] + RedRowS[tid * 4 + 3];
            float sp = RedRowP[tid * 4 + 0] + RedRowP[tid * 4 + 1] +
                       RedRowP[tid * 4 + 2] + RedRowP[tid * 4 + 3];
            g_prow_sum[cb][RG + tid] = s;
            g_prow_pos[cb][RG + tid] = sp;
            float c = RedColS[tid * 2 + 0] + RedColS[tid * 2 + 1];
            float cp = RedColP[tid * 2 + 0] + RedColP[tid * 2 + 1];
            g_pcol_sum[rb][CG + tid] = c;
            g_pcol_pos[rb][CG + tid] = cp;
        }
    }
}

// ---------------- kernel 3: partial reduce + log terms + last-block final ----------------
__global__ void reduce_kernel(float* __restrict__ out) {
    __shared__ float red[4][8][32];
    __shared__ int isLast;
    int tid = threadIdx.x;
    int lane = tid & 31, w = tid >> 5;
    int i = blockIdx.x * 32 + lane;
    float rs = 0.f, rp = 0.f, cs = 0.f, cp = 0.f;
#pragma unroll
    for (int j = 0; j < 8; j++) {
        int t = w * 8 + j;
        rs += g_prow_sum[t][i];
        rp += g_prow_pos[t][i];
        cs += g_pcol_sum[t][i];
        cp += g_pcol_pos[t][i];
    }
    red[0][w][lane] = rs;
    red[1][w][lane] = rp;
    red[2][w][lane] = cs;
    red[3][w][lane] = cp;
    __syncthreads();
    if (w == 0) {
        float trs = 0.f, trp = 0.f, tcs = 0.f, tcp = 0.f;
#pragma unroll
        for (int k = 0; k < 8; k++) {
            trs += red[0][k][lane];
            trp += red[1][k][lane];
            tcs += red[2][k][lane];
            tcp += red[3][k][lane];
        }
        float contrib = LAM * (logf(trp) - logf(trs + EPS)) +
                        (1.0f - LAM) * (logf(tcp) - logf(tcs + EPS));
#pragma unroll
        for (int off = 16; off > 0; off >>= 1)
            contrib += __shfl_xor_sync(0xFFFFFFFF, contrib, off);
        if (lane == 0) g_blocksum[blockIdx.x] = contrib;
    }
    // last-block final reduction (canonical threadfence pattern)
    __threadfence();
    if (tid == 0) {
        int tkt = atomicAdd(&g_count, 1);
        isLast = (tkt == 255);
    }
    __syncthreads();
    if (isLast) {
        float v = g_blocksum[tid];
#pragma unroll
        for (int off = 16; off > 0; off >>= 1)
            v += __shfl_xor_sync(0xFFFFFFFF, v, off);
        __shared__ float ws[8];
        if (lane == 0) ws[w] = v;
        __syncthreads();
        if (w == 0) {
            float s = (lane < 8) ? ws[lane] : 0.0f;
#pragma unroll
            for (int off = 4; off > 0; off >>= 1)
                s += __shfl_xor_sync(0xFFFFFFFF, s, off);
            if (lane == 0) {
                out[0] = -s * (1.0f / (float)N);
                g_count = 0;   // reset for next graph replay
            }
        }
    }
}

// ---------------- launch ----------------
extern "C" void kernel_launch(void* const* d_in, const int* in_sizes, int n_in,
                              void* d_out, int out_size) {
    const float* z_mp = (const float*)d_in[0];
    const float* z_sc = (const float*)d_in[1];
    const int* pos = (const int*)d_in[2];
    float* out = (float*)d_out;

    cudaFuncSetAttribute(pair_kernel, cudaFuncAttributeMaxDynamicSharedMemorySize,
                         SMEM_BYTES);

    normalize_kernel<<<2 * N / 8, 256>>>(z_mp, z_sc);
    pair_kernel<<<NPAIRS, 256, SMEM_BYTES>>>(pos);
    reduce_kernel<<<256, 256>>>(out);
}

// round 17
// speedup vs baseline: 1.4595x; 1.0028x over previous
#include <cuda_runtime.h>
#include <cuda_bf16.h>
#include <cstdint>
#include <stdint.h>
#include <math.h>

#define N 8192
#define D 64
#define LAM 0.5f
#define EPS 1e-8f
#define NT 64
#define NPAIRS 2080

// ---------------- device scratch ----------------
__device__ uint16_t g_zn_mp[N * 32];   // e4m3-packed normalized rows (64 B/row)
__device__ uint16_t g_zn_sc[N * 32];
__device__ float g_prow_sum[NT][N];
__device__ float g_prow_pos[NT][N];
__device__ float g_pcol_sum[NT][N];
__device__ float g_pcol_pos[NT][N];
__device__ float g_blocksum[256];
__device__ int g_count;   // zero-init; reset by last block each launch

// smem layout (dynamic)
#define OFF_AF   0            // A frags, 2 phases x 8192
#define OFF_BF   16384        // B frags, 2 phases x 8192
#define OFF_PB   32768        // P bits 2048
#define OFF_QB   34816        // Q bits 2048
#define OFF_RRS  36864        // RedRowS [128][4] f32
#define OFF_RRP  38912
#define OFF_RCS  40960        // RedColS [128][2] f32
#define OFF_RCP  41984
#define SMEM_BYTES 43008

__device__ __forceinline__ float exp_tau(float x) {
    float y = x * 1.80336880f;   // (1/0.8) * log2(e)
    float r;
    asm("ex2.approx.ftz.f32 %0, %1;" : "=f"(r) : "f"(y));
    return r;
}

__device__ __forceinline__ void mma_fp8(float* c, const uint4& a, const uint2& b) {
    asm volatile(
        "mma.sync.aligned.m16n8k32.row.col.f32.e4m3.e4m3.f32 "
        "{%0,%1,%2,%3}, {%4,%5,%6,%7}, {%8,%9}, {%0,%1,%2,%3};"
        : "+f"(c[0]), "+f"(c[1]), "+f"(c[2]), "+f"(c[3])
        : "r"(a.x), "r"(a.y), "r"(a.z), "r"(a.w), "r"(b.x), "r"(b.y));
}

// ---------------- kernel 1: normalize + quantize, 8 rows per warp (ILP) ----------------
// grid 256 x block 256: 2048 warps, each handles 8 consecutive rows of the
// 16384 logical rows (0..8191 = mp, 8192..16383 = sc).
__global__ void normalize_kernel(const float* __restrict__ zmp,
                                 const float* __restrict__ zsc) {
    int gwarp = (blockIdx.x * blockDim.x + threadIdx.x) >> 5;   // 0..2047
    int lane = threadIdx.x & 31;
    int row0 = gwarp * 8;

    float2 v[8];
#pragma unroll
    for (int j = 0; j < 8; j++) {
        int row = row0 + j;
        const float* src = (row < N) ? (zmp + (size_t)row * D)
                                     : (zsc + (size_t)(row - N) * D);
        v[j] = *(const float2*)(src + 2 * lane);   // 8 independent LDG.64
    }
#pragma unroll
    for (int j = 0; j < 8; j++) {
        float s = v[j].x * v[j].x + v[j].y * v[j].y;
#pragma unroll
        for (int off = 16; off > 0; off >>= 1)
            s += __shfl_xor_sync(0xFFFFFFFF, s, off);
        float inv = rsqrtf(s);
        uint16_t packed;
        asm("cvt.rn.satfinite.e4m3x2.f32 %0, %1, %2;"
            : "=h"(packed) : "f"(v[j].y * inv), "f"(v[j].x * inv));
        int row = row0 + j;
        uint16_t* dst = (row < N) ? (g_zn_mp + (size_t)row * 32)
                                  : (g_zn_sc + (size_t)(row - N) * 32);
        dst[lane] = packed;
    }
}

// ---------------- kernel 2: symmetric-pair tile kernel (fp8 HMMA) ----------------
__global__ __launch_bounds__(256, 2)
void pair_kernel(const int* __restrict__ pos) {
    extern __shared__ char smem[];
    unsigned* Pbits = (unsigned*)(smem + OFF_PB);
    unsigned* Qbits = (unsigned*)(smem + OFF_QB);
    float* RedRowS = (float*)(smem + OFF_RRS);   // [128][4]
    float* RedRowP = (float*)(smem + OFF_RRP);
    float* RedColS = (float*)(smem + OFF_RCS);   // [128][2]
    float* RedColP = (float*)(smem + OFF_RCP);

    const int tid = threadIdx.x;
    const int lane = tid & 31;
    const int wid = tid >> 5;
    const int wm = wid >> 2;   // 0..1 : 64-row slab
    const int wn = wid & 3;    // 0..3 : 32-col slab
    const int q = lane >> 2, l4 = lane & 3;

    // triangular decode: blockIdx.x -> (b0, b1), b0 <= b1
    int b0 = 0, rem = blockIdx.x;
    while (rem >= NT - b0) { rem -= NT - b0; b0++; }
    int b1 = b0 + rem;

    const int sh = (lane & 7) * 4;
    const int widx = lane >> 3;
    const int* Pbase = pos + (size_t)(b0 * 128 + wid) * N + b1 * 128 + lane * 4;
    const int* Qbase = pos + (size_t)(b1 * 128 + wid) * N + b0 * 128 + lane * 4;

    // ==== CTA head: pos (DRAM, long pole) issued FIRST; z (L2-hot) under it ====
    {
        int4 pb[8], qb[8];
        // pos batch 1: 16 independent streaming LDG.128 in flight
#pragma unroll
        for (int j = 0; j < 8; j++) {
            pb[j] = __ldcs((const int4*)(Pbase + (size_t)j * 8 * N));
            qb[j] = __ldcs((const int4*)(Qbase + (size_t)j * 8 * N));
        }

        // z loads for BOTH phases (L2-hot after wave 1), issued under pos batch 1
        const int m = tid >> 1, hc = (tid & 1) * 2;   // 2 uint4 per tile per thread
        const char* A0g = (const char*)g_zn_mp + (size_t)(b0 * 128) * 64;
        const char* B0g = (const char*)g_zn_sc + (size_t)(b1 * 128) * 64;
        const char* A1g = (const char*)g_zn_mp + (size_t)(b1 * 128) * 64;
        const char* B1g = (const char*)g_zn_sc + (size_t)(b0 * 128) * 64;
        uint4 za0[2], zb0[2], za1[2], zb1[2];
#pragma unroll
        for (int i = 0; i < 2; i++) {
            za0[i] = *(const uint4*)(A0g + m * 64 + (hc + i) * 16);
            zb0[i] = *(const uint4*)(B0g + m * 64 + (hc + i) * 16);
            za1[i] = *(const uint4*)(A1g + m * 64 + (hc + i) * 16);
            zb1[i] = *(const uint4*)(B1g + m * 64 + (hc + i) * 16);
        }

        // store all 4 z tiles to frag smem (consumes z regs; pos still in flight)
#pragma unroll
        for (int i = 0; i < 2; i++) {
            int c4 = hc + i;
            int ks = c4 >> 1, kh = c4 & 1;
            int aoff = ((ks * 8 + (m >> 4)) * 32 + (m & 7) * 4) * 4 + ((m >> 3) & 1) + 2 * kh;
            int boff = ((ks * 16 + (m >> 3)) * 32 + (m & 7) * 4) * 2 + kh;
            uint32_t* Af0 = (uint32_t*)(smem + OFF_AF);
            uint32_t* Af1 = (uint32_t*)(smem + OFF_AF + 8192);
            uint32_t* Bf0 = (uint32_t*)(smem + OFF_BF);
            uint32_t* Bf1 = (uint32_t*)(smem + OFF_BF + 8192);
            Af0[aoff] = za0[i].x; Af0[aoff + 4] = za0[i].y; Af0[aoff + 8] = za0[i].z; Af0[aoff + 12] = za0[i].w;
            Af1[aoff] = za1[i].x; Af1[aoff + 4] = za1[i].y; Af1[aoff + 8] = za1[i].z; Af1[aoff + 12] = za1[i].w;
            Bf0[boff] = zb0[i].x; Bf0[boff + 2] = zb0[i].y; Bf0[boff + 4] = zb0[i].z; Bf0[boff + 6] = zb0[i].w;
            Bf1[boff] = zb1[i].x; Bf1[boff + 2] = zb1[i].y; Bf1[boff + 4] = zb1[i].z; Bf1[boff + 6] = zb1[i].w;
        }

        // pack+store pos batch 1
#pragma unroll
        for (int j = 0; j < 8; j++) {
            int r = wid + j * 8;
            unsigned pw = ((pb[j].x & 1) | ((pb[j].y & 1) << 1) | ((pb[j].z & 1) << 2) |
                           ((pb[j].w & 1) << 3)) << sh;
            unsigned qw = ((qb[j].x & 1) | ((qb[j].y & 1) << 1) | ((qb[j].z & 1) << 2) |
                           ((qb[j].w & 1) << 3)) << sh;
            pw |= __shfl_xor_sync(0xFFFFFFFF, pw, 1);
            pw |= __shfl_xor_sync(0xFFFFFFFF, pw, 2);
            pw |= __shfl_xor_sync(0xFFFFFFFF, pw, 4);
            qw |= __shfl_xor_sync(0xFFFFFFFF, qw, 1);
            qw |= __shfl_xor_sync(0xFFFFFFFF, qw, 2);
            qw |= __shfl_xor_sync(0xFFFFFFFF, qw, 4);
            if ((lane & 7) == 0) {
                Pbits[r * 4 + widx] = pw;
                Qbits[r * 4 + widx] = qw;
            }
        }
        // pos batch 2
#pragma unroll
        for (int j = 0; j < 8; j++) {
            pb[j] = __ldcs((const int4*)(Pbase + (size_t)(j + 8) * 8 * N));
            qb[j] = __ldcs((const int4*)(Qbase + (size_t)(j + 8) * 8 * N));
        }
#pragma unroll
        for (int j = 0; j < 8; j++) {
            int r = wid + (j + 8) * 8;
            unsigned pw = ((pb[j].x & 1) | ((pb[j].y & 1) << 1) | ((pb[j].z & 1) << 2) |
                           ((pb[j].w & 1) << 3)) << sh;
            unsigned qw = ((qb[j].x & 1) | ((qb[j].y & 1) << 1) | ((qb[j].z & 1) << 2) |
                           ((qb[j].w & 1) << 3)) << sh;
            pw |= __shfl_xor_sync(0xFFFFFFFF, pw, 1);
            pw |= __shfl_xor_sync(0xFFFFFFFF, pw, 2);
            pw |= __shfl_xor_sync(0xFFFFFFFF, pw, 4);
            qw |= __shfl_xor_sync(0xFFFFFFFF, qw, 1);
            qw |= __shfl_xor_sync(0xFFFFFFFF, qw, 2);
            qw |= __shfl_xor_sync(0xFFFFFFFF, qw, 4);
            if ((lane & 7) == 0) {
                Pbits[r * 4 + widx] = pw;
                Qbits[r * 4 + widx] = qw;
            }
        }
    }
    __syncthreads();   // all frags + pos bits visible

    const int nphase = (b0 == b1) ? 1 : 2;

    for (int t = 0; t < nphase; t++) {
        const int rb = t ? b1 : b0;
        const int cb = t ? b0 : b1;
        const int RG = rb * 128, CG = cb * 128;
        const uint32_t* Asm32 = (const uint32_t*)(smem + OFF_AF + t * 8192);
        const uint32_t* Bsm32 = (const uint32_t*)(smem + OFF_BF + t * 8192);

        if (t == 1) __syncthreads();   // phase-0 finalize reads of reds done

        // ---- fp8 tensor-core mainloop: warp tile 64x32, 2 K-steps of 32 ----
        float acc[4][4][4];
#pragma unroll
        for (int mt = 0; mt < 4; mt++)
#pragma unroll
            for (int nt = 0; nt < 4; nt++)
#pragma unroll
                for (int r = 0; r < 4; r++) acc[mt][nt][r] = 0.0f;

#pragma unroll
        for (int ks = 0; ks < 2; ks++) {
            uint4 a[4];
            uint2 b[4];
#pragma unroll
            for (int mt = 0; mt < 4; mt++)
                a[mt] = *(const uint4*)(Asm32 + ((ks * 8 + wm * 4 + mt) * 32 + lane) * 4);
#pragma unroll
            for (int nt = 0; nt < 4; nt++)
                b[nt] = *(const uint2*)(Bsm32 + ((ks * 16 + wn * 4 + nt) * 32 + lane) * 2);
#pragma unroll
            for (int mt = 0; mt < 4; mt++)
#pragma unroll
                for (int nt = 0; nt < 4; nt++)
                    mma_fp8(acc[mt][nt], a[mt], b[nt]);
        }

        // ---- epilogue: MUFU exp + bitmask pos pairing + partial reductions ----
        const unsigned* rowB = t ? Qbits : Pbits;
        const unsigned* colB = t ? Pbits : Qbits;

        unsigned cw[4][2][2];
#pragma unroll
        for (int nt = 0; nt < 4; nt++)
#pragma unroll
            for (int p = 0; p < 2; p++) {
                int c = wn * 32 + nt * 8 + 2 * l4 + p;
#pragma unroll
                for (int ws = 0; ws < 2; ws++)
                    cw[nt][p][ws] = colB[c * 4 + wm * 2 + ws];
            }

        float rs[8], rp2[8];
        float cs[4][2], cp2[4][2];
#pragma unroll
        for (int nt = 0; nt < 4; nt++) { cs[nt][0] = cs[nt][1] = 0.f; cp2[nt][0] = cp2[nt][1] = 0.f; }

#pragma unroll
        for (int mt = 0; mt < 4; mt++) {
            const int wsel = (mt >= 2) ? 1 : 0;
#pragma unroll
            for (int half = 0; half < 2; half++) {
                int rloc = mt * 16 + q + 8 * half;
                int r = wm * 64 + rloc;
                int bitidx = (mt & 1) * 16 + q + 8 * half;
                unsigned rw = rowB[r * 4 + wn];
                float rsum = 0.f, rpos = 0.f;
#pragma unroll
                for (int nt = 0; nt < 4; nt++) {
                    float v0 = exp_tau(acc[mt][nt][half * 2 + 0]);
                    float v1 = exp_tau(acc[mt][nt][half * 2 + 1]);
                    unsigned rbits = rw >> (nt * 8 + 2 * l4);
                    rsum += v0 + v1;
                    if (rbits & 1u) rpos += v0;
                    if (rbits & 2u) rpos += v1;
                    cs[nt][0] += v0;
                    cs[nt][1] += v1;
                    if ((cw[nt][0][wsel] >> bitidx) & 1u) cp2[nt][0] += v0;
                    if ((cw[nt][1][wsel] >> bitidx) & 1u) cp2[nt][1] += v1;
                }
                rsum += __shfl_xor_sync(0xFFFFFFFF, rsum, 1);
                rsum += __shfl_xor_sync(0xFFFFFFFF, rsum, 2);
                rpos += __shfl_xor_sync(0xFFFFFFFF, rpos, 1);
                rpos += __shfl_xor_sync(0xFFFFFFFF, rpos, 2);
                rs[mt * 2 + half] = rsum;
                rp2[mt * 2 + half] = rpos;
            }
        }
#pragma unroll
        for (int nt = 0; nt < 4; nt++)
#pragma unroll
            for (int p = 0; p < 2; p++) {
                float v = cs[nt][p];
                v += __shfl_xor_sync(0xFFFFFFFF, v, 4);
                v += __shfl_xor_sync(0xFFFFFFFF, v, 8);
                v += __shfl_xor_sync(0xFFFFFFFF, v, 16);
                cs[nt][p] = v;
                float w = cp2[nt][p];
                w += __shfl_xor_sync(0xFFFFFFFF, w, 4);
                w += __shfl_xor_sync(0xFFFFFFFF, w, 8);
                w += __shfl_xor_sync(0xFFFFFFFF, w, 16);
                cp2[nt][p] = w;
            }

        // dedicated reds smem: no pre-write barrier needed
        if (l4 == 0) {
#pragma unroll
            for (int mt = 0; mt < 4; mt++)
#pragma unroll
                for (int half = 0; half < 2; half++) {
                    int r = wm * 64 + mt * 16 + q + 8 * half;
                    RedRowS[r * 4 + wn] = rs[mt * 2 + half];
                    RedRowP[r * 4 + wn] = rp2[mt * 2 + half];
                }
        }
        if (lane < 4) {
#pragma unroll
            for (int nt = 0; nt < 4; nt++)
#pragma unroll
                for (int p = 0; p < 2; p++) {
                    int c = wn * 32 + nt * 8 + 2 * lane + p;
                    RedColS[c * 2 + wm] = cs[nt][p];
                    RedColP[c * 2 + wm] = cp2[nt][p];
                }
        }
        __syncthreads();

        if (tid < 128) {
            float s = RedRowS[tid * 4 + 0] + RedRowS[tid * 4 + 1] +
                      RedRowS[tid * 4 + 2] + RedRowS[tid * 4 + 3];
            float sp = RedRowP[tid * 4 + 0] + RedRowP[tid * 4 + 1] +
                       RedRowP[tid * 4 + 2] + RedRowP[tid * 4 + 3];
            g_prow_sum[cb][RG + tid] = s;
            g_prow_pos[cb][RG + tid] = sp;
            float c = RedColS[tid * 2 + 0] + RedColS[tid * 2 + 1];
            float cp = RedColP[tid * 2 + 0] + RedColP[tid * 2 + 1];
            g_pcol_sum[rb][CG + tid] = c;
            g_pcol_pos[rb][CG + tid] = cp;
        }
    }
}

// ---------------- kernel 3: partial reduce + log terms + last-block final ----------------
__global__ void reduce_kernel(float* __restrict__ out) {
    __shared__ float red[4][8][32];
    __shared__ int isLast;
    int tid = threadIdx.x;
    int lane = tid & 31, w = tid >> 5;
    int i = blockIdx.x * 32 + lane;
    float rs = 0.f, rp = 0.f, cs = 0.f, cp = 0.f;
#pragma unroll
    for (int j = 0; j < 8; j++) {
        int t = w * 8 + j;
        rs += g_prow_sum[t][i];
        rp += g_prow_pos[t][i];
        cs += g_pcol_sum[t][i];
        cp += g_pcol_pos[t][i];
    }
    red[0][w][lane] = rs;
    red[1][w][lane] = rp;
    red[2][w][lane] = cs;
    red[3][w][lane] = cp;
    __syncthreads();
    if (w == 0) {
        float trs = 0.f, trp = 0.f, tcs = 0.f, tcp = 0.f;
#pragma unroll
        for (int k = 0; k < 8; k++) {
            trs += red[0][k][lane];
            trp += red[1][k][lane];
            tcs += red[2][k][lane];
            tcp += red[3][k][lane];
        }
        float contrib = LAM * (logf(trp) - logf(trs + EPS)) +
                        (1.0f - LAM) * (logf(tcp) - logf(tcs + EPS));
#pragma unroll
        for (int off = 16; off > 0; off >>= 1)
            contrib += __shfl_xor_sync(0xFFFFFFFF, contrib, off);
        if (lane == 0) g_blocksum[blockIdx.x] = contrib;
    }
    // last-block final reduction
    __threadfence();
    if (tid == 0) {
        int tkt = atomicAdd(&g_count, 1);
        isLast = (tkt == 255);
    }
    __syncthreads();
    if (isLast) {
        float v = g_blocksum[tid];
#pragma unroll
        for (int off = 16; off > 0; off >>= 1)
            v += __shfl_xor_sync(0xFFFFFFFF, v, off);
        __shared__ float ws[8];
        if (lane == 0) ws[w] = v;
        __syncthreads();
        if (w == 0) {
            float s = (lane < 8) ? ws[lane] : 0.0f;
#pragma unroll
            for (int off = 4; off > 0; off >>= 1)
                s += __shfl_xor_sync(0xFFFFFFFF, s, off);
            if (lane == 0) {
                out[0] = -s * (1.0f / (float)N);
                g_count = 0;   // reset for next graph replay
            }
        }
    }
}

// ---------------- launch ----------------
extern "C" void kernel_launch(void* const* d_in, const int* in_sizes, int n_in,
                              void* d_out, int out_size) {
    const float* z_mp = (const float*)d_in[0];
    const float* z_sc = (const float*)d_in[1];
    const int* pos = (const int*)d_in[2];
    float* out = (float*)d_out;

    cudaFuncSetAttribute(pair_kernel, cudaFuncAttributeMaxDynamicSharedMemorySize,
                         SMEM_BYTES);

    normalize_kernel<<<256, 256>>>(z_mp, z_sc);
    pair_kernel<<<NPAIRS, 256, SMEM_BYTES>>>(pos);
    reduce_kernel<<<256, 256>>>(out);
}